// round 5
// baseline (speedup 1.0000x reference)
#include <cuda_runtime.h>
#include <cstdint>

#define VMAX 100000
#define EMAX 1600000

// ---------------- device scratch (no allocations allowed) ----------------
__device__ int   g_rowptr[VMAX + 1];
__device__ int   g_cnt[VMAX];
__device__ int   g_cols[EMAX];
__device__ float g_vals[EMAX];
__device__ float g_xn[(size_t)VMAX * 128];     // BN'ed input, layer0 X0 + residual
__device__ float g_bufA[(size_t)VMAX * 256];
__device__ float g_bufB[(size_t)VMAX * 256];
__device__ float g_bufC[(size_t)VMAX * 256];
__device__ float g_bufD[(size_t)VMAX * 256];
__device__ float g_sum[64];
__device__ float g_sq[64];
__device__ float g_scale[64];
__device__ float g_shift[64];

// ---------------- CSR build ----------------
__global__ void k_zero_cnt(int V) {
    int i = blockIdx.x * blockDim.x + threadIdx.x;
    if (i < V) g_cnt[i] = 0;
}

__global__ void k_hist(const int* __restrict__ rows, int E) {
    int e = blockIdx.x * blockDim.x + threadIdx.x;
    if (e < E) atomicAdd(&g_cnt[rows[e]], 1);
}

// single-block exclusive scan of g_cnt -> g_rowptr
__global__ void k_scan(int V) {
    __shared__ int sh[1024];
    __shared__ int s_carry;
    int tid = threadIdx.x;
    if (tid == 0) s_carry = 0;
    __syncthreads();
    for (int base = 0; base < V; base += 1024) {
        int i = base + tid;
        int v = (i < V) ? g_cnt[i] : 0;
        sh[tid] = v;
        __syncthreads();
        for (int off = 1; off < 1024; off <<= 1) {
            int t = (tid >= off) ? sh[tid - off] : 0;
            __syncthreads();
            sh[tid] += t;
            __syncthreads();
        }
        int carry = s_carry;
        if (i < V) g_rowptr[i] = carry + sh[tid] - v;
        __syncthreads();
        if (tid == 1023) s_carry = carry + sh[1023];
        __syncthreads();
    }
    if (threadIdx.x == 0) g_rowptr[V] = s_carry;
}

__global__ void k_fill(const int* __restrict__ rows, const int* __restrict__ cols,
                       const float* __restrict__ vals, int E) {
    int e = blockIdx.x * blockDim.x + threadIdx.x;
    if (e >= E) return;
    int r = rows[e];
    int pos = g_rowptr[r] + atomicAdd(&g_cnt[r], 1);
    g_cols[pos] = cols[e];
    g_vals[pos] = vals[e];
}

// ---------------- BatchNorm ----------------
__global__ void k_zero_stats() {
    int i = threadIdx.x;
    if (i < 64) { g_sum[i] = 0.f; g_sq[i] = 0.f; }
}

// input x is (B, C, V): one slab = (b,c) contiguous V floats
__global__ void k_stats_in(const float* __restrict__ x, int V, int C) {
    __shared__ float ss[256], sq[256];
    int slab = blockIdx.y;
    int c = slab % C;
    const float* p = x + (size_t)slab * V;
    float s = 0.f, q = 0.f;
    for (int i = blockIdx.x * blockDim.x + threadIdx.x; i < V; i += gridDim.x * blockDim.x) {
        float t = p[i];
        s += t; q += t * t;
    }
    int tid = threadIdx.x;
    ss[tid] = s; sq[tid] = q;
    __syncthreads();
    for (int o = 128; o > 0; o >>= 1) {
        if (tid < o) { ss[tid] += ss[tid + o]; sq[tid] += sq[tid + o]; }
        __syncthreads();
    }
    if (tid == 0) { atomicAdd(&g_sum[c], ss[0]); atomicAdd(&g_sq[c], sq[0]); }
}

// T is vertex-major (V, 64, 4) -> 256 floats per vertex, thread f fixed
__global__ void k_stats_vm(const float* __restrict__ T, int V) {
    int f = threadIdx.x;        // 0..255
    float s = 0.f, q = 0.f;
    for (int v = blockIdx.x; v < V; v += gridDim.x) {
        float t = T[(size_t)v * 256 + f];
        s += t; q += t * t;
    }
    s += __shfl_xor_sync(0xffffffffu, s, 1);
    s += __shfl_xor_sync(0xffffffffu, s, 2);
    q += __shfl_xor_sync(0xffffffffu, q, 1);
    q += __shfl_xor_sync(0xffffffffu, q, 2);
    if ((f & 3) == 0) {
        int c = f >> 2;
        atomicAdd(&g_sum[c], s);
        atomicAdd(&g_sq[c], q);
    }
}

__global__ void k_finalize(const float* __restrict__ gamma, const float* __restrict__ beta,
                           int C, float invN) {
    int c = threadIdx.x;
    if (c >= C) return;
    float m = g_sum[c] * invN;
    float var = g_sq[c] * invN - m * m;
    float inv = rsqrtf(var + 1e-5f);
    float sc = gamma[c] * inv;
    g_scale[c] = sc;
    g_shift[c] = beta[c] - sc * m;
}

// normalize + transpose (B,32,V) -> (V,32,4). Block: 128 thr, 32 vertices.
__global__ void __launch_bounds__(128) k_apply_in(const float* __restrict__ x, int V) {
    __shared__ float sh[32 * 129];
    int v0 = blockIdx.x * 32;
    // read coalesced from (B,C,V), scale/shift, store to shared transposed
    for (int j = threadIdx.x; j < 4096; j += 128) {
        int b = j >> 10;            // /1024
        int r = j & 1023;
        int c = r >> 5;
        int vl = r & 31;
        int v = v0 + vl;
        float t = 0.f;
        if (v < V) t = x[((size_t)(b * 32 + c)) * V + v];
        sh[vl * 129 + c * 4 + b] = g_scale[c] * t + g_shift[c];
    }
    __syncthreads();
    for (int j = threadIdx.x; j < 4096; j += 128) {
        int vl = j >> 7;
        int f = j & 127;
        int v = v0 + vl;
        if (v < V) g_xn[(size_t)v * 128 + f] = sh[vl * 129 + f];
    }
}

// normalize in place layout (V,64,4), elementwise float4 (one channel per float4)
__global__ void k_apply_vm(float4* __restrict__ dst, const float4* __restrict__ src, int n4) {
    int i = blockIdx.x * blockDim.x + threadIdx.x;
    if (i >= n4) return;
    int c = i & 63;
    float s = g_scale[c], h = g_shift[c];
    float4 v = src[i];
    v.x = v.x * s + h; v.y = v.y * s + h; v.z = v.z * s + h; v.w = v.w * s + h;
    dst[i] = v;
}

// ---------------- SpMM: y[row] = alpha * sum_e w_e * x[col_e] + beta * z[row] ----------------
// warp handles (row, 128-float chunk); float4 per lane
__global__ void __launch_bounds__(256) k_spmm(float* __restrict__ y, const float* __restrict__ x,
                                              const float* __restrict__ z,
                                              float alpha, float beta, int V, int F, int c2) {
    int gw = (blockIdx.x * 256 + threadIdx.x) >> 5;
    int lane = threadIdx.x & 31;
    int row = gw >> c2;
    if (row >= V) return;
    int ch = gw & ((1 << c2) - 1);
    int off = ch * 128 + lane * 4;
    const float* xb = x + off;
    int beg = g_rowptr[row], end = g_rowptr[row + 1];
    float4 acc = make_float4(0.f, 0.f, 0.f, 0.f);
    int e = beg;
    for (; e + 2 <= end; e += 2) {
        int   c0 = g_cols[e],  c1 = g_cols[e + 1];
        float w0 = g_vals[e],  w1 = g_vals[e + 1];
        float4 v0 = *(const float4*)(xb + (size_t)c0 * F);
        float4 v1 = *(const float4*)(xb + (size_t)c1 * F);
        acc.x += w0 * v0.x; acc.y += w0 * v0.y; acc.z += w0 * v0.z; acc.w += w0 * v0.w;
        acc.x += w1 * v1.x; acc.y += w1 * v1.y; acc.z += w1 * v1.z; acc.w += w1 * v1.w;
    }
    if (e < end) {
        int c0 = g_cols[e]; float w0 = g_vals[e];
        float4 v0 = *(const float4*)(xb + (size_t)c0 * F);
        acc.x += w0 * v0.x; acc.y += w0 * v0.y; acc.z += w0 * v0.z; acc.w += w0 * v0.w;
    }
    size_t oi = (size_t)row * F + off;
    if (beta != 0.f) {
        float4 zv = *(const float4*)(z + oi);
        acc.x = alpha * acc.x + beta * zv.x;
        acc.y = alpha * acc.y + beta * zv.y;
        acc.z = alpha * acc.z + beta * zv.z;
        acc.w = alpha * acc.w + beta * zv.w;
    } else {
        acc.x *= alpha; acc.y *= alpha; acc.z *= alpha; acc.w *= alpha;
    }
    *(float4*)(y + oi) = acc;
}

// ---------------- paired einsum: OUT[v][o][b] (+)= sum_c XA*wA + XB*wB ----------------
template <int CIN, int COUT, bool INIT, bool RELU>
__global__ void __launch_bounds__(128) k_ein2(float* __restrict__ out,
                                              const float* __restrict__ XA,
                                              const float* __restrict__ XB,
                                              const float* __restrict__ wA,
                                              const float* __restrict__ wB,
                                              const float* __restrict__ bias, int V) {
    constexpr int TPV = COUT / 8;        // threads per vertex
    constexpr int VPB = 128 / TPV;       // vertices per block
    __shared__ float swA[CIN * COUT];
    __shared__ float swB[CIN * COUT];
    __shared__ float sbias[COUT];
    for (int i = threadIdx.x; i < CIN * COUT; i += 128) { swA[i] = wA[i]; swB[i] = wB[i]; }
    if (INIT) for (int i = threadIdx.x; i < COUT; i += 128) sbias[i] = bias[i];
    __syncthreads();
    int v = blockIdx.x * VPB + threadIdx.x / TPV;
    if (v >= V) return;
    int og = (threadIdx.x % TPV) * 8;

    const float4* xa = (const float4*)(XA + (size_t)v * CIN * 4);
    const float4* xb = (const float4*)(XB + (size_t)v * CIN * 4);
    float acc[8][4];
#pragma unroll
    for (int o = 0; o < 8; o++)
#pragma unroll
        for (int b = 0; b < 4; b++) acc[o][b] = 0.f;

#pragma unroll 4
    for (int c = 0; c < CIN; c++) {
        float4 a = __ldg(xa + c);
        float4 b4 = __ldg(xb + c);
        const float* wra = &swA[c * COUT + og];
        const float* wrb = &swB[c * COUT + og];
#pragma unroll
        for (int o = 0; o < 8; o++) {
            float wa = wra[o];
            float wb = wrb[o];
            acc[o][0] += a.x * wa; acc[o][0] += b4.x * wb;
            acc[o][1] += a.y * wa; acc[o][1] += b4.y * wb;
            acc[o][2] += a.z * wa; acc[o][2] += b4.z * wb;
            acc[o][3] += a.w * wa; acc[o][3] += b4.w * wb;
        }
    }

    float4* o4 = (float4*)(out + (size_t)v * COUT * 4 + og * 4);
#pragma unroll
    for (int o = 0; o < 8; o++) {
        float4 r = make_float4(acc[o][0], acc[o][1], acc[o][2], acc[o][3]);
        if (INIT) {
            float bb = sbias[og + o];
            r.x += bb; r.y += bb; r.z += bb; r.w += bb;
        } else {
            float4 p = o4[o];
            r.x += p.x; r.y += p.y; r.z += p.z; r.w += p.w;
        }
        if (RELU) {
            r.x = fmaxf(r.x, 0.f); r.y = fmaxf(r.y, 0.f);
            r.z = fmaxf(r.z, 0.f); r.w = fmaxf(r.w, 0.f);
        }
        o4[o] = r;
    }
}

// ---------------- final residual + transpose to (B,32,V) ----------------
__global__ void __launch_bounds__(128) k_final(float* __restrict__ out,
                                               const float* __restrict__ R, int V) {
    __shared__ float sh[32 * 129];
    int v0 = blockIdx.x * 32;
    for (int j = threadIdx.x; j < 4096; j += 128) {
        int vl = j >> 7;
        int f = j & 127;
        int v = v0 + vl;
        float t = 0.f;
        if (v < V) {
            size_t idx = (size_t)v * 128 + f;
            t = fmaxf(R[idx] + g_xn[idx], 0.f);
        }
        sh[vl * 129 + f] = t;
    }
    __syncthreads();
    for (int j = threadIdx.x; j < 4096; j += 128) {
        int b = j >> 10;
        int r = j & 1023;
        int c = r >> 5;
        int vl = r & 31;
        int v = v0 + vl;
        if (v < V) out[((size_t)(b * 32 + c)) * V + v] = sh[vl * 129 + c * 4 + b];
    }
}

// ---------------- host orchestration ----------------
extern "C" void kernel_launch(void* const* d_in, const int* in_sizes, int n_in,
                              void* d_out, int out_size) {
    const float* x        = (const float*)d_in[0];
    const int*   ei       = (const int*)d_in[1];
    const float* lap_vals = (const float*)d_in[2];
    const float* in_bn_g  = (const float*)d_in[3];
    const float* in_bn_b  = (const float*)d_in[4];
    const float* in_w     = (const float*)d_in[5];
    const float* in_b     = (const float*)d_in[6];
    const float* h0_bn_g  = (const float*)d_in[7];
    const float* h0_bn_b  = (const float*)d_in[8];
    const float* h0_w     = (const float*)d_in[9];
    const float* h0_b     = (const float*)d_in[10];
    const float* h1_bn_g  = (const float*)d_in[11];
    const float* h1_bn_b  = (const float*)d_in[12];
    const float* h1_w     = (const float*)d_in[13];
    const float* h1_b     = (const float*)d_in[14];

    const int V = in_sizes[0] / 128;      // B*Cin = 128
    const int E = in_sizes[1] / 2;
    const int* rows = ei;
    const int* cols = ei + E;
    const float invN = 1.0f / (4.0f * (float)V);

    float *bufA, *bufB, *bufC, *bufD, *xn;
    cudaGetSymbolAddress((void**)&bufA, g_bufA);
    cudaGetSymbolAddress((void**)&bufB, g_bufB);
    cudaGetSymbolAddress((void**)&bufC, g_bufC);
    cudaGetSymbolAddress((void**)&bufD, g_bufD);
    cudaGetSymbolAddress((void**)&xn, g_xn);

    const int NBV = (V + 255) / 256;
    const int NBE = (E + 255) / 256;
    const int NB32 = (V + 31) / 32;

    // ---- CSR build ----
    k_zero_cnt<<<NBV, 256>>>(V);
    k_hist<<<NBE, 256>>>(rows, E);
    k_scan<<<1, 1024>>>(V);
    k_zero_cnt<<<NBV, 256>>>(V);
    k_fill<<<NBE, 256>>>(rows, cols, lap_vals, E);

    // ---- layer 0: BN(32) + Cheb 32->64 ----
    k_zero_stats<<<1, 64>>>();
    k_stats_in<<<dim3(8, 128), 256>>>(x, V, 32);
    k_finalize<<<1, 64>>>(in_bn_g, in_bn_b, 32, invN);
    k_apply_in<<<NB32, 128>>>(x, V);   // -> g_xn (V,32,4)

    const int SPB128 = (V * 32 + 255) / 256;       // F=128: 1 warp/row
    const int SPB256 = (V * 64 + 255) / 256;       // F=256: 2 warps/row

    k_spmm<<<SPB128, 256>>>(bufA, xn, nullptr, 1.f, 0.f, V, 128, 0);            // X1
    k_spmm<<<SPB128, 256>>>(bufB, bufA, xn, 2.f, -1.f, V, 128, 0);              // X2
    k_ein2<32, 64, true, false><<<(V + 15) / 16, 128>>>(bufC, xn, bufA,
        in_w + 0 * 2048, in_w + 1 * 2048, in_b, V);
    k_spmm<<<SPB128, 256>>>(bufD, bufB, bufA, 2.f, -1.f, V, 128, 0);            // X3
    k_ein2<32, 64, false, true><<<(V + 15) / 16, 128>>>(bufC, bufB, bufD,
        in_w + 2 * 2048, in_w + 3 * 2048, nullptr, V);
    // T1 = bufC (V,64,4), relu applied

    // ---- layer 1: BN(64) + Cheb 64->64 ----
    k_zero_stats<<<1, 64>>>();
    k_stats_vm<<<512, 256>>>(bufC, V);
    k_finalize<<<1, 64>>>(h0_bn_g, h0_bn_b, 64, invN);
    k_apply_vm<<<(V * 64 + 255) / 256, 256>>>((float4*)bufA, (const float4*)bufC, V * 64);

    k_spmm<<<SPB256, 256>>>(bufB, bufA, nullptr, 1.f, 0.f, V, 256, 1);          // X1
    k_spmm<<<SPB256, 256>>>(bufD, bufB, bufA, 2.f, -1.f, V, 256, 1);            // X2
    k_ein2<64, 64, true, false><<<(V + 15) / 16, 128>>>(bufC, bufA, bufB,
        h0_w + 0 * 4096, h0_w + 1 * 4096, h0_b, V);
    k_spmm<<<SPB256, 256>>>(bufA, bufD, bufB, 2.f, -1.f, V, 256, 1);            // X3
    k_ein2<64, 64, false, true><<<(V + 15) / 16, 128>>>(bufC, bufD, bufA,
        h0_w + 2 * 4096, h0_w + 3 * 4096, nullptr, V);
    // T2 = bufC (V,64,4), relu applied

    // ---- layer 2: BN(64) + Cheb 64->32, no relu ----
    k_zero_stats<<<1, 64>>>();
    k_stats_vm<<<512, 256>>>(bufC, V);
    k_finalize<<<1, 64>>>(h1_bn_g, h1_bn_b, 64, invN);
    k_apply_vm<<<(V * 64 + 255) / 256, 256>>>((float4*)bufA, (const float4*)bufC, V * 64);

    k_spmm<<<SPB256, 256>>>(bufB, bufA, nullptr, 1.f, 0.f, V, 256, 1);          // X1
    k_spmm<<<SPB256, 256>>>(bufD, bufB, bufA, 2.f, -1.f, V, 256, 1);            // X2
    k_ein2<64, 32, true, false><<<(V + 31) / 32, 128>>>(bufC, bufA, bufB,
        h1_w + 0 * 2048, h1_w + 1 * 2048, h1_b, V);
    k_spmm<<<SPB256, 256>>>(bufA, bufD, bufB, 2.f, -1.f, V, 256, 1);            // X3
    k_ein2<64, 32, false, false><<<(V + 31) / 32, 128>>>(bufC, bufD, bufA,
        h1_w + 2 * 2048, h1_w + 3 * 2048, nullptr, V);

    // ---- residual + relu + transpose to (B,32,V) ----
    k_final<<<NB32, 128>>>((float*)d_out, bufC, V);
    (void)n_in; (void)out_size;
}

// round 6
// speedup vs baseline: 1.3494x; 1.3494x over previous
#include <cuda_runtime.h>
#include <cuda_fp16.h>
#include <cstdint>

#define VMAX 100000
#define EMAX 1600000

// ---------------- device scratch (no allocations allowed) ----------------
__device__ int    g_rowptr[VMAX + 1];
__device__ int    g_cnt[VMAX];
__device__ int    g_cols[EMAX];
__device__ float  g_vals[EMAX];
__device__ __half g_xn[(size_t)VMAX * 128];   // BN'ed input (V,32,4), residual + layer0 X0
__device__ __half g_x0[(size_t)VMAX * 256];
__device__ __half g_x1[(size_t)VMAX * 256];
__device__ __half g_x2[(size_t)VMAX * 256];
__device__ __half g_x3[(size_t)VMAX * 256];
__device__ __half g_t [(size_t)VMAX * 256];   // einsum output / next layer input
__device__ float  g_sum[64];
__device__ float  g_sq[64];
__device__ float  g_scale[64];
__device__ float  g_shift[64];

// ---------------- CSR build ----------------
__global__ void k_zero_cnt(int V) {
    int i = blockIdx.x * blockDim.x + threadIdx.x;
    if (i < V) g_cnt[i] = 0;
}

__global__ void k_hist(const int* __restrict__ rows, int E) {
    int e = blockIdx.x * blockDim.x + threadIdx.x;
    if (e < E) atomicAdd(&g_cnt[rows[e]], 1);
}

__global__ void k_scan(int V) {
    __shared__ int sh[1024];
    __shared__ int s_carry;
    int tid = threadIdx.x;
    if (tid == 0) s_carry = 0;
    __syncthreads();
    for (int base = 0; base < V; base += 1024) {
        int i = base + tid;
        int v = (i < V) ? g_cnt[i] : 0;
        sh[tid] = v;
        __syncthreads();
        for (int off = 1; off < 1024; off <<= 1) {
            int t = (tid >= off) ? sh[tid - off] : 0;
            __syncthreads();
            sh[tid] += t;
            __syncthreads();
        }
        int carry = s_carry;
        if (i < V) g_rowptr[i] = carry + sh[tid] - v;
        __syncthreads();
        if (tid == 1023) s_carry = carry + sh[1023];
        __syncthreads();
    }
    if (threadIdx.x == 0) g_rowptr[V] = s_carry;
}

__global__ void k_fill(const int* __restrict__ rows, const int* __restrict__ cols,
                       const float* __restrict__ vals, int E) {
    int e = blockIdx.x * blockDim.x + threadIdx.x;
    if (e >= E) return;
    int r = rows[e];
    int pos = g_rowptr[r] + atomicAdd(&g_cnt[r], 1);
    g_cols[pos] = cols[e];
    g_vals[pos] = vals[e];
}

// ---------------- BatchNorm ----------------
__global__ void k_zero_stats() {
    int i = threadIdx.x;
    if (i < 64) { g_sum[i] = 0.f; g_sq[i] = 0.f; }
}

// input x is fp32 (B, C, V): one slab = (b,c) contiguous V floats
__global__ void k_stats_in(const float* __restrict__ x, int V, int C) {
    __shared__ float ss[256], sq[256];
    int slab = blockIdx.y;
    int c = slab % C;
    const float* p = x + (size_t)slab * V;
    float s = 0.f, q = 0.f;
    for (int i = blockIdx.x * blockDim.x + threadIdx.x; i < V; i += gridDim.x * blockDim.x) {
        float t = p[i];
        s += t; q += t * t;
    }
    int tid = threadIdx.x;
    ss[tid] = s; sq[tid] = q;
    __syncthreads();
    for (int o = 128; o > 0; o >>= 1) {
        if (tid < o) { ss[tid] += ss[tid + o]; sq[tid] += sq[tid + o]; }
        __syncthreads();
    }
    if (tid == 0) { atomicAdd(&g_sum[c], ss[0]); atomicAdd(&g_sq[c], sq[0]); }
}

// T is fp16 vertex-major (V, 64, 4) = 128 half2 per vertex; thread -> fixed half2 slot
__global__ void __launch_bounds__(128) k_stats_vm_h(const __half2* __restrict__ T, int V) {
    int t = threadIdx.x;     // half2 slot 0..127; channel = t>>1
    float s = 0.f, q = 0.f;
    for (int v = blockIdx.x; v < V; v += gridDim.x) {
        float2 f = __half22float2(T[(size_t)v * 128 + t]);
        s += f.x + f.y;
        q += f.x * f.x + f.y * f.y;
    }
    s += __shfl_xor_sync(0xffffffffu, s, 1);
    q += __shfl_xor_sync(0xffffffffu, q, 1);
    if ((t & 1) == 0) {
        int c = t >> 1;
        atomicAdd(&g_sum[c], s);
        atomicAdd(&g_sq[c], q);
    }
}

__global__ void k_finalize(const float* __restrict__ gamma, const float* __restrict__ beta,
                           int C, float invN) {
    int c = threadIdx.x;
    if (c >= C) return;
    float m = g_sum[c] * invN;
    float var = g_sq[c] * invN - m * m;
    float inv = rsqrtf(var + 1e-5f);
    float sc = gamma[c] * inv;
    g_scale[c] = sc;
    g_shift[c] = beta[c] - sc * m;
}

// normalize + transpose (B,32,V) fp32 -> (V,32,4) fp16
__global__ void __launch_bounds__(128) k_apply_in(const float* __restrict__ x, int V) {
    __shared__ float sh[32 * 129];
    int v0 = blockIdx.x * 32;
    for (int j = threadIdx.x; j < 4096; j += 128) {
        int b = j >> 10;
        int r = j & 1023;
        int c = r >> 5;
        int vl = r & 31;
        int v = v0 + vl;
        float t = 0.f;
        if (v < V) t = x[((size_t)(b * 32 + c)) * V + v];
        sh[vl * 129 + c * 4 + b] = g_scale[c] * t + g_shift[c];
    }
    __syncthreads();
    for (int j = threadIdx.x; j < 4096; j += 128) {
        int vl = j >> 7;
        int f = j & 127;
        int v = v0 + vl;
        if (v < V) g_xn[(size_t)v * 128 + f] = __float2half_rn(sh[vl * 129 + f]);
    }
}

// normalize fp16 (V,64,4): i indexes uint2 = 4 halfs = batch quad of channel (i&63)
__global__ void k_apply_vm_h(uint2* __restrict__ dst, const uint2* __restrict__ src, int n) {
    int i = blockIdx.x * blockDim.x + threadIdx.x;
    if (i >= n) return;
    int c = i & 63;
    float s = g_scale[c], h = g_shift[c];
    uint2 raw = src[i];
    float2 fa = __half22float2(*(__half2*)&raw.x);
    float2 fb = __half22float2(*(__half2*)&raw.y);
    fa.x = fa.x * s + h; fa.y = fa.y * s + h;
    fb.x = fb.x * s + h; fb.y = fb.y * s + h;
    uint2 o;
    *(__half2*)&o.x = __floats2half2_rn(fa.x, fa.y);
    *(__half2*)&o.y = __floats2half2_rn(fb.x, fb.y);
    dst[i] = o;
}

// ---------------- SpMM fp16: y[row] = alpha * sum_e w_e * x[col_e] + beta * z[row] ----
// F = halfs per row (128 or 256). One warp per row; lane handles F/32 halfs.
template <int F>
__global__ void __launch_bounds__(256) k_spmm_h(__half* __restrict__ y,
                                                const __half* __restrict__ x,
                                                const __half* __restrict__ z,
                                                float alpha, float beta, int V) {
    constexpr int HPL = F / 32;   // 4 or 8
    int row = (blockIdx.x * 256 + threadIdx.x) >> 5;
    if (row >= V) return;
    int lane = threadIdx.x & 31;
    const __half* xb = x + lane * HPL;
    int beg = g_rowptr[row], end = g_rowptr[row + 1];
    float acc[HPL];
#pragma unroll
    for (int i = 0; i < HPL; i++) acc[i] = 0.f;

    int e = beg;
    for (; e + 4 <= end; e += 4) {
        int   cc[4];
        float ww[4];
#pragma unroll
        for (int j = 0; j < 4; j++) { cc[j] = g_cols[e + j]; ww[j] = g_vals[e + j]; }
#pragma unroll
        for (int j = 0; j < 4; j++) {
            const __half* p = xb + (size_t)cc[j] * F;
            float w = ww[j];
            if constexpr (HPL == 8) {
                uint4 raw = *(const uint4*)p;
                float2 f;
                f = __half22float2(*(__half2*)&raw.x); acc[0] += w * f.x; acc[1] += w * f.y;
                f = __half22float2(*(__half2*)&raw.y); acc[2] += w * f.x; acc[3] += w * f.y;
                f = __half22float2(*(__half2*)&raw.z); acc[4] += w * f.x; acc[5] += w * f.y;
                f = __half22float2(*(__half2*)&raw.w); acc[6] += w * f.x; acc[7] += w * f.y;
            } else {
                uint2 raw = *(const uint2*)p;
                float2 f;
                f = __half22float2(*(__half2*)&raw.x); acc[0] += w * f.x; acc[1] += w * f.y;
                f = __half22float2(*(__half2*)&raw.y); acc[2] += w * f.x; acc[3] += w * f.y;
            }
        }
    }
    for (; e < end; e++) {
        int c0 = g_cols[e];
        float w = g_vals[e];
        const __half* p = xb + (size_t)c0 * F;
        if constexpr (HPL == 8) {
            uint4 raw = *(const uint4*)p;
            float2 f;
            f = __half22float2(*(__half2*)&raw.x); acc[0] += w * f.x; acc[1] += w * f.y;
            f = __half22float2(*(__half2*)&raw.y); acc[2] += w * f.x; acc[3] += w * f.y;
            f = __half22float2(*(__half2*)&raw.z); acc[4] += w * f.x; acc[5] += w * f.y;
            f = __half22float2(*(__half2*)&raw.w); acc[6] += w * f.x; acc[7] += w * f.y;
        } else {
            uint2 raw = *(const uint2*)p;
            float2 f;
            f = __half22float2(*(__half2*)&raw.x); acc[0] += w * f.x; acc[1] += w * f.y;
            f = __half22float2(*(__half2*)&raw.y); acc[2] += w * f.x; acc[3] += w * f.y;
        }
    }

    size_t oi = (size_t)row * F + lane * HPL;
    if (beta != 0.f) {
#pragma unroll
        for (int i = 0; i < HPL; i += 2) {
            float2 f = __half22float2(*(const __half2*)(z + oi + i));
            acc[i]     = alpha * acc[i]     + beta * f.x;
            acc[i + 1] = alpha * acc[i + 1] + beta * f.y;
        }
    } else if (alpha != 1.f) {
#pragma unroll
        for (int i = 0; i < HPL; i++) acc[i] *= alpha;
    }
    if constexpr (HPL == 8) {
        uint4 o;
        *(__half2*)&o.x = __floats2half2_rn(acc[0], acc[1]);
        *(__half2*)&o.y = __floats2half2_rn(acc[2], acc[3]);
        *(__half2*)&o.z = __floats2half2_rn(acc[4], acc[5]);
        *(__half2*)&o.w = __floats2half2_rn(acc[6], acc[7]);
        *(uint4*)(y + oi) = o;
    } else {
        uint2 o;
        *(__half2*)&o.x = __floats2half2_rn(acc[0], acc[1]);
        *(__half2*)&o.y = __floats2half2_rn(acc[2], acc[3]);
        *(uint2*)(y + oi) = o;
    }
}

// ---------------- paired einsum: OUT[v][o][b] (+)= sum_c XA*wA + XB*wB (fp16 I/O) -------
template <int CIN, int COUT, bool INIT, bool RELU>
__global__ void __launch_bounds__(128) k_ein2h(__half* __restrict__ out,
                                               const __half* __restrict__ XA,
                                               const __half* __restrict__ XB,
                                               const float* __restrict__ wA,
                                               const float* __restrict__ wB,
                                               const float* __restrict__ bias, int V) {
    constexpr int TPV = COUT / 8;
    constexpr int VPB = 128 / TPV;
    __shared__ float swA[CIN * COUT];
    __shared__ float swB[CIN * COUT];
    __shared__ float sbias[COUT];
    for (int i = threadIdx.x; i < CIN * COUT; i += 128) { swA[i] = wA[i]; swB[i] = wB[i]; }
    if (INIT) for (int i = threadIdx.x; i < COUT; i += 128) sbias[i] = bias[i];
    __syncthreads();
    int v = blockIdx.x * VPB + threadIdx.x / TPV;
    if (v >= V) return;
    int og = (threadIdx.x % TPV) * 8;

    const uint2* xa = (const uint2*)(XA + (size_t)v * CIN * 4);
    const uint2* xb = (const uint2*)(XB + (size_t)v * CIN * 4);
    float acc[8][4];
#pragma unroll
    for (int o = 0; o < 8; o++)
#pragma unroll
        for (int b = 0; b < 4; b++) acc[o][b] = 0.f;

#pragma unroll 4
    for (int c = 0; c < CIN; c++) {
        uint2 ra = __ldg(xa + c);
        uint2 rb = __ldg(xb + c);
        float2 a01 = __half22float2(*(__half2*)&ra.x);
        float2 a23 = __half22float2(*(__half2*)&ra.y);
        float2 b01 = __half22float2(*(__half2*)&rb.x);
        float2 b23 = __half22float2(*(__half2*)&rb.y);
        float4 A0 = *(const float4*)&swA[c * COUT + og];
        float4 A1 = *(const float4*)&swA[c * COUT + og + 4];
        float4 B0 = *(const float4*)&swB[c * COUT + og];
        float4 B1 = *(const float4*)&swB[c * COUT + og + 4];
        float wa[8] = {A0.x, A0.y, A0.z, A0.w, A1.x, A1.y, A1.z, A1.w};
        float wb[8] = {B0.x, B0.y, B0.z, B0.w, B1.x, B1.y, B1.z, B1.w};
#pragma unroll
        for (int o = 0; o < 8; o++) {
            acc[o][0] = fmaf(a01.x, wa[o], acc[o][0]);
            acc[o][0] = fmaf(b01.x, wb[o], acc[o][0]);
            acc[o][1] = fmaf(a01.y, wa[o], acc[o][1]);
            acc[o][1] = fmaf(b01.y, wb[o], acc[o][1]);
            acc[o][2] = fmaf(a23.x, wa[o], acc[o][2]);
            acc[o][2] = fmaf(b23.x, wb[o], acc[o][2]);
            acc[o][3] = fmaf(a23.y, wa[o], acc[o][3]);
            acc[o][3] = fmaf(b23.y, wb[o], acc[o][3]);
        }
    }

    __half2* o2 = (__half2*)(out + (size_t)v * COUT * 4 + og * 4);
#pragma unroll
    for (int o = 0; o < 8; o++) {
        float rx = acc[o][0], ry = acc[o][1], rz = acc[o][2], rw = acc[o][3];
        if (INIT) {
            float bb = sbias[og + o];
            rx += bb; ry += bb; rz += bb; rw += bb;
        } else {
            float2 p0 = __half22float2(o2[2 * o]);
            float2 p1 = __half22float2(o2[2 * o + 1]);
            rx += p0.x; ry += p0.y; rz += p1.x; rw += p1.y;
        }
        if (RELU) {
            rx = fmaxf(rx, 0.f); ry = fmaxf(ry, 0.f);
            rz = fmaxf(rz, 0.f); rw = fmaxf(rw, 0.f);
        }
        o2[2 * o]     = __floats2half2_rn(rx, ry);
        o2[2 * o + 1] = __floats2half2_rn(rz, rw);
    }
}

// ---------------- final residual + relu + transpose to fp32 (B,32,V) ----------------
__global__ void __launch_bounds__(128) k_final(float* __restrict__ out,
                                               const __half* __restrict__ R, int V) {
    __shared__ float sh[32 * 129];
    int v0 = blockIdx.x * 32;
    for (int j = threadIdx.x; j < 4096; j += 128) {
        int vl = j >> 7;
        int f = j & 127;
        int v = v0 + vl;
        float t = 0.f;
        if (v < V) {
            size_t idx = (size_t)v * 128 + f;
            t = fmaxf(__half2float(R[idx]) + __half2float(g_xn[idx]), 0.f);
        }
        sh[vl * 129 + f] = t;
    }
    __syncthreads();
    for (int j = threadIdx.x; j < 4096; j += 128) {
        int b = j >> 10;
        int r = j & 1023;
        int c = r >> 5;
        int vl = r & 31;
        int v = v0 + vl;
        if (v < V) out[((size_t)(b * 32 + c)) * V + v] = sh[vl * 129 + c * 4 + b];
    }
}

// ---------------- host orchestration ----------------
extern "C" void kernel_launch(void* const* d_in, const int* in_sizes, int n_in,
                              void* d_out, int out_size) {
    const float* x        = (const float*)d_in[0];
    const int*   ei       = (const int*)d_in[1];
    const float* lap_vals = (const float*)d_in[2];
    const float* in_bn_g  = (const float*)d_in[3];
    const float* in_bn_b  = (const float*)d_in[4];
    const float* in_w     = (const float*)d_in[5];
    const float* in_b     = (const float*)d_in[6];
    const float* h0_bn_g  = (const float*)d_in[7];
    const float* h0_bn_b  = (const float*)d_in[8];
    const float* h0_w     = (const float*)d_in[9];
    const float* h0_b     = (const float*)d_in[10];
    const float* h1_bn_g  = (const float*)d_in[11];
    const float* h1_bn_b  = (const float*)d_in[12];
    const float* h1_w     = (const float*)d_in[13];
    const float* h1_b     = (const float*)d_in[14];

    const int V = in_sizes[0] / 128;      // B*Cin = 128
    const int E = in_sizes[1] / 2;
    const int* rows = ei;
    const int* cols = ei + E;
    const float invN = 1.0f / (4.0f * (float)V);

    __half *xn, *x0, *x1, *x2, *x3, *tb;
    cudaGetSymbolAddress((void**)&xn, g_xn);
    cudaGetSymbolAddress((void**)&x0, g_x0);
    cudaGetSymbolAddress((void**)&x1, g_x1);
    cudaGetSymbolAddress((void**)&x2, g_x2);
    cudaGetSymbolAddress((void**)&x3, g_x3);
    cudaGetSymbolAddress((void**)&tb, g_t);

    const int NBV  = (V + 255) / 256;
    const int NBE  = (E + 255) / 256;
    const int NB32 = (V + 31) / 32;
    const int NBW  = (V + 7) / 8;          // one warp per row, 256-thread blocks
    const int NE64 = (V + 15) / 16;        // ein blocks for COUT=64
    const int NE32 = (V + 31) / 32;        // ein blocks for COUT=32
    const int NAPP = (V * 64 + 255) / 256;

    // ---- CSR build ----
    k_zero_cnt<<<NBV, 256>>>(V);
    k_hist<<<NBE, 256>>>(rows, E);
    k_scan<<<1, 1024>>>(V);
    k_zero_cnt<<<NBV, 256>>>(V);
    k_fill<<<NBE, 256>>>(rows, cols, lap_vals, E);

    // ---- layer 0: BN(32) + Cheb 32->64 ----
    k_zero_stats<<<1, 64>>>();
    k_stats_in<<<dim3(8, 128), 256>>>(x, V, 32);
    k_finalize<<<1, 64>>>(in_bn_g, in_bn_b, 32, invN);
    k_apply_in<<<NB32, 128>>>(x, V);                                     // -> g_xn

    k_spmm_h<128><<<NBW, 256>>>(x1, xn, nullptr, 1.f, 0.f, V);           // X1
    k_spmm_h<128><<<NBW, 256>>>(x2, x1, xn, 2.f, -1.f, V);               // X2
    k_ein2h<32, 64, true, false><<<NE64, 128>>>(tb, xn, x1,
        in_w + 0 * 2048, in_w + 1 * 2048, in_b, V);
    k_spmm_h<128><<<NBW, 256>>>(x3, x2, x1, 2.f, -1.f, V);               // X3
    k_ein2h<32, 64, false, true><<<NE64, 128>>>(tb, x2, x3,
        in_w + 2 * 2048, in_w + 3 * 2048, nullptr, V);
    // T1 = g_t (V,64,4) fp16, relu applied

    // ---- layer 1: BN(64) + Cheb 64->64 ----
    k_zero_stats<<<1, 64>>>();
    k_stats_vm_h<<<1024, 128>>>((const __half2*)tb, V);
    k_finalize<<<1, 64>>>(h0_bn_g, h0_bn_b, 64, invN);
    k_apply_vm_h<<<NAPP, 256>>>((uint2*)x0, (const uint2*)tb, V * 64);   // X0

    k_spmm_h<256><<<NBW, 256>>>(x1, x0, nullptr, 1.f, 0.f, V);
    k_spmm_h<256><<<NBW, 256>>>(x2, x1, x0, 2.f, -1.f, V);
    k_ein2h<64, 64, true, false><<<NE64, 128>>>(tb, x0, x1,
        h0_w + 0 * 4096, h0_w + 1 * 4096, h0_b, V);
    k_spmm_h<256><<<NBW, 256>>>(x3, x2, x1, 2.f, -1.f, V);
    k_ein2h<64, 64, false, true><<<NE64, 128>>>(tb, x2, x3,
        h0_w + 2 * 4096, h0_w + 3 * 4096, nullptr, V);
    // T2 = g_t (V,64,4) fp16, relu applied

    // ---- layer 2: BN(64) + Cheb 64->32, no relu ----
    k_zero_stats<<<1, 64>>>();
    k_stats_vm_h<<<1024, 128>>>((const __half2*)tb, V);
    k_finalize<<<1, 64>>>(h1_bn_g, h1_bn_b, 64, invN);
    k_apply_vm_h<<<NAPP, 256>>>((uint2*)x0, (const uint2*)tb, V * 64);

    k_spmm_h<256><<<NBW, 256>>>(x1, x0, nullptr, 1.f, 0.f, V);
    k_spmm_h<256><<<NBW, 256>>>(x2, x1, x0, 2.f, -1.f, V);
    k_ein2h<64, 32, true, false><<<NE32, 128>>>(tb, x0, x1,
        h1_w + 0 * 2048, h1_w + 1 * 2048, h1_b, V);
    k_spmm_h<256><<<NBW, 256>>>(x3, x2, x1, 2.f, -1.f, V);
    k_ein2h<64, 32, false, false><<<NE32, 128>>>(tb, x2, x3,
        h1_w + 2 * 2048, h1_w + 3 * 2048, nullptr, V);
    // R = g_t (V,32,4) fp16

    // ---- residual + relu + transpose to (B,32,V) fp32 ----
    k_final<<<NB32, 128>>>((float*)d_out, tb, V);
    (void)n_in; (void)out_size;
}